// round 14
// baseline (speedup 1.0000x reference)
#include <cuda_runtime.h>
#include <cuda_fp16.h>
#include <math.h>
#include <stdint.h>

// Problem shape (fixed by setup_inputs)
#define Bc 4
#define Lc 4096
#define Dc 1024
#define Hc 2048
#define Mrows (Bc * Lc)            // 16384
#define BLD ((size_t)Mrows * Dc)   // 16,777,216

// ---------------------------------------------------------------------------
// Scratch regions (float units)  (identical to R13)
// ---------------------------------------------------------------------------
__device__ float g_buf[108527616];

#define OFF_RIRM ((size_t)0)
#define OFF_HBUF ((size_t)33554432)
#define OFF_X1   ((size_t)50331648)
#define OFF_XN   ((size_t)67108864)
#define OFF_XN2  ((size_t)75497472)
#define OFF_FF   ((size_t)83886080)
#define OFF_WT   ((size_t)100663296)
#define OFF_AB   ((size_t)106954752)
#define OFF_CIN  ((size_t)108003328)

#define WSEG_H ((size_t)2097152)   // halfs per weight matrix

// ---------------------------------------------------------------------------
// helpers
// ---------------------------------------------------------------------------
__device__ __forceinline__ float sigmoidf_(float x) {
    return 1.0f / (1.0f + expf(-x));
}
__device__ __forceinline__ void cp16(void* dst, const void* src) {
    uint32_t d = (uint32_t)__cvta_generic_to_shared(dst);
    asm volatile("cp.async.cg.shared.global [%0], [%1], 16;\n" :: "r"(d), "l"(src));
}

// k-permuted fp16 storage: within each 16-k block, pair order
// [0,1,8,9,2,3,10,11,4,5,12,13,6,7,14,15]. psl(k) for even k gives the stored
// index of that pair's first element (odd partner is psl(k)+1).
__device__ __forceinline__ int psl(int k) {
    const int p = (k >> 1) & 7;
    return (k & ~15) | ((((p & 3) << 1) | (p >> 2)) << 1);
}

__device__ __forceinline__ void mma_f16(float4& c, uint32_t a0, uint32_t a1,
                                        uint32_t a2, uint32_t a3,
                                        uint32_t b0, uint32_t b1) {
    asm volatile(
        "mma.sync.aligned.m16n8k16.row.col.f32.f16.f16.f32 "
        "{%0,%1,%2,%3}, {%4,%5,%6,%7}, {%8,%9}, {%0,%1,%2,%3};\n"
        : "+f"(c.x), "+f"(c.y), "+f"(c.z), "+f"(c.w)
        : "r"(a0), "r"(a1), "r"(a2), "r"(a3), "r"(b0), "r"(b1));
}

// ---------------------------------------------------------------------------
// Fused: rmsnorm of x (blocks [0, Mrows)) + weight fp16-permute prep
// ---------------------------------------------------------------------------
__global__ void __launch_bounds__(256) norm1_prep(
    const float* __restrict__ x, const float* __restrict__ g,
    __half* __restrict__ outx,
    const float* __restrict__ w0, const float* __restrict__ w1,
    const float* __restrict__ w2, const float* __restrict__ w3,
    const float* __restrict__ w4, const float* __restrict__ w5,
    __half* __restrict__ wdst)
{
    const int t = threadIdx.x;
    if (blockIdx.x < Mrows) {
        const int row = blockIdx.x;
        const float4* xr = reinterpret_cast<const float4*>(x) + (size_t)row * (Dc / 4);
        float4 v = xr[t];
        float ss = v.x * v.x + v.y * v.y + v.z * v.z + v.w * v.w;
        #pragma unroll
        for (int off = 16; off > 0; off >>= 1)
            ss += __shfl_down_sync(0xffffffffu, ss, off);
        __shared__ float warp_s[8];
        if ((t & 31) == 0) warp_s[t >> 5] = ss;
        __syncthreads();
        float tot = 0.f;
        #pragma unroll
        for (int i = 0; i < 8; i++) tot += warp_s[i];
        const float scale = rsqrtf(tot * (1.0f / Dc) + 1e-6f);
        float4 gv = reinterpret_cast<const float4*>(g)[t];
        __half* d = outx + (size_t)row * Dc;
        const int k = 4 * t;
        *reinterpret_cast<__half2*>(d + psl(k)) =
            __floats2half2_rn(v.x * scale * gv.x, v.y * scale * gv.y);
        *reinterpret_cast<__half2*>(d + psl(k + 2)) =
            __floats2half2_rn(v.z * scale * gv.z, v.w * scale * gv.w);
    } else {
        const size_t i4 = (size_t)(blockIdx.x - Mrows) * 256 + t;
        const int seg = (int)(i4 >> 19);            // 524288 float4 per matrix
        const size_t off = (i4 & 524287) * 4;
        const float* src;
        switch (seg) {
            case 0: src = w0; break; case 1: src = w1; break;
            case 2: src = w2; break; case 3: src = w3; break;
            case 4: src = w4; break; default: src = w5; break;
        }
        float4 v = *reinterpret_cast<const float4*>(src + off);
        __half* d = wdst + seg * WSEG_H + (off & ~(size_t)15);
        const int j = (int)(off & 15);
        *reinterpret_cast<__half2*>(d + (psl(j) & 15))     = __floats2half2_rn(v.x, v.y);
        *reinterpret_cast<__half2*>(d + (psl(j + 2) & 15)) = __floats2half2_rn(v.z, v.w);
    }
}

// ---------------------------------------------------------------------------
// RMSNorm: fp16 (plain) in -> k-permuted fp16 out (used for norm2 on X1)
// ---------------------------------------------------------------------------
__global__ void __launch_bounds__(256) rmsnorm_h_kernel(
    const __half* __restrict__ x, const float* __restrict__ g,
    __half* __restrict__ out)
{
    const int row = blockIdx.x;
    const int t = threadIdx.x;
    const __half2* xr = reinterpret_cast<const __half2*>(x + (size_t)row * Dc);
    const __half2 h0 = xr[2 * t];
    const __half2 h1 = xr[2 * t + 1];
    const float2 v01 = __half22float2(h0);
    const float2 v23 = __half22float2(h1);
    float ss = v01.x * v01.x + v01.y * v01.y + v23.x * v23.x + v23.y * v23.y;
    #pragma unroll
    for (int off = 16; off > 0; off >>= 1)
        ss += __shfl_down_sync(0xffffffffu, ss, off);
    __shared__ float warp_s[8];
    if ((t & 31) == 0) warp_s[t >> 5] = ss;
    __syncthreads();
    float tot = 0.f;
    #pragma unroll
    for (int i = 0; i < 8; i++) tot += warp_s[i];
    const float scale = rsqrtf(tot * (1.0f / Dc) + 1e-6f);
    float4 gv = reinterpret_cast<const float4*>(g)[t];
    __half* d = out + (size_t)row * Dc;
    const int k = 4 * t;
    *reinterpret_cast<__half2*>(d + psl(k)) =
        __floats2half2_rn(v01.x * scale * gv.x, v01.y * scale * gv.y);
    *reinterpret_cast<__half2*>(d + psl(k + 2)) =
        __floats2half2_rn(v23.x * scale * gv.z, v23.y * scale * gv.w);
}

// ---------------------------------------------------------------------------
// fp16 HMMA GEMM with FMA-pipe assist on dual modes.
// A, W are k-permuted fp16. BM=128, BN=64, BK=32, 256 threads
// (8 warps: 4m x 2n), warp tile 32x32, m16n8k16 HMMA, fp32 accumulate.
// 3-stage cp.async pipeline; smem row stride 96 B -> conflict-free LDS.64.
// HYBRID (MODE 0/1, K=1024): tensor covers k<960 (30 iters); k 960..1023 is
// computed on the idle FMA pipe from a persistent 36 KB smem slice, one
// k-pair per iteration, accumulating into the SAME fp32 acc registers.
// MODE 0: dual -> RIRM interleaved (rem,ri) + fused chunk aggregates to AB.
// MODE 1: dual -> FF = fp16 permuted( z1 * silu(z2) )
// MODE 2: single -> x1 = fp16( z1 + bias + fp32 residual )
// MODE 3: single -> out = fp32 z1 + bias + fp16 residual
// ---------------------------------------------------------------------------
template <int MODE>
__global__ void __launch_bounds__(256, 2) gemm_f16(
    const __half* __restrict__ A,
    const __half* __restrict__ W1,
    const __half* __restrict__ W2,
    const float* __restrict__ b1,
    const float* __restrict__ b2,
    const float* __restrict__ res,   // MODE2: fp32 residual
    const __half* __restrict__ resh, // MODE3: fp16 residual
    float* __restrict__ out,         // MODE1/2: __half* underneath
    uint2* __restrict__ rirm,        // MODE0: interleaved (rem,ri) plane
    float2* __restrict__ ab,         // MODE0: chunk aggregates
    int M, int N, int K)
{
    constexpr bool DUAL = (MODE == 0 || MODE == 1);
    constexpr bool HYB  = DUAL;                    // K==1024 on dual modes
    constexpr int STAGEB = DUAL ? 24576 : 18432;   // bytes per stage
    constexpr int FOFF = 3 * STAGEB;               // persistent FFMA slice
    extern __shared__ char sm[];

    const int tid  = threadIdx.x;
    const int lane = tid & 31;
    const int wid  = tid >> 5;
    const int wm = wid >> 1;           // 0..3
    const int wn = wid & 1;            // 0..1
    const int gid = lane >> 2;         // 0..7
    const int tig = lane & 3;          // 0..3
    const int bm = blockIdx.y * 128;
    const int bn = blockIdx.x * 64;
    const int niter = HYB ? ((K - 64) >> 5) : (K >> 5);   // 30 for hybrid

    float4 acc1[2][4];
    float4 acc2[2][4];
    #pragma unroll
    for (int i = 0; i < 2; i++)
        #pragma unroll
        for (int j = 0; j < 4; j++) {
            acc1[i][j] = make_float4(0.f, 0.f, 0.f, 0.f);
            acc2[i][j] = make_float4(0.f, 0.f, 0.f, 0.f);
        }

    auto load_stage = [&](int slot, int it) {
        char* st = sm + slot * STAGEB;
        const int k0 = it << 5;
        #pragma unroll
        for (int i = 0; i < 2; i++) {
            int q = tid + (i << 8);
            int r = q >> 2, c = q & 3;
            cp16(st + r * 96 + c * 16, A + (size_t)(bm + r) * K + k0 + c * 8);
        }
        {
            int r = tid >> 2, c = tid & 3;
            cp16(st + 12288 + r * 96 + c * 16,
                 W1 + (size_t)(bn + r) * K + k0 + c * 8);
            if (DUAL)
                cp16(st + 18432 + r * 96 + c * 16,
                     W2 + (size_t)(bn + r) * K + k0 + c * 8);
        }
    };

    // HYBRID: load the persistent k-slice [K-64, K) once (group 0 w/ stage 0).
    if (HYB) {
        const int ks = K - 64;
        #pragma unroll
        for (int i = 0; i < 4; i++) {           // A2: 128 rows x 64 halves
            int q = tid + (i << 8);
            int r = q >> 3, c = q & 7;
            cp16(sm + FOFF + r * 144 + c * 16,
                 A + (size_t)(bm + r) * K + ks + c * 8);
        }
        #pragma unroll
        for (int i = 0; i < 2; i++) {           // B1x/B2x: 64 rows x 64 halves
            int q = tid + (i << 8);
            int r = q >> 3, c = q & 7;
            cp16(sm + FOFF + 18432 + r * 144 + c * 16,
                 W1 + (size_t)(bn + r) * K + ks + c * 8);
            cp16(sm + FOFF + 27648 + r * 144 + c * 16,
                 W2 + (size_t)(bn + r) * K + ks + c * 8);
        }
    }

    load_stage(0, 0);
    asm volatile("cp.async.commit_group;\n");
    load_stage(1, 1);
    asm volatile("cp.async.commit_group;\n");

    // One k-pair of FMA-pipe work, accumulating into the tensor accs.
    auto ffma_pair = [&](int p) {
        const __half2* A2h = reinterpret_cast<const __half2*>(sm + FOFF);
        const __half2* B1h = reinterpret_cast<const __half2*>(sm + FOFF + 18432);
        const __half2* B2h = reinterpret_cast<const __half2*>(sm + FOFF + 27648);
        float2 av[2][2];
        #pragma unroll
        for (int mf = 0; mf < 2; mf++)
            #pragma unroll
            for (int h = 0; h < 2; h++)
                av[mf][h] = __half22float2(
                    A2h[(wm * 32 + mf * 16 + gid + h * 8) * 36 + p]);
        #pragma unroll
        for (int nf = 0; nf < 4; nf++) {
            const int c0 = wn * 32 + nf * 8 + 2 * tig;
            const float2 b0 = __half22float2(B1h[c0 * 36 + p]);
            const float2 b1 = __half22float2(B1h[(c0 + 1) * 36 + p]);
            const float2 d0 = __half22float2(B2h[c0 * 36 + p]);
            const float2 d1 = __half22float2(B2h[(c0 + 1) * 36 + p]);
            #pragma unroll
            for (int mf = 0; mf < 2; mf++) {
                acc1[mf][nf].x = fmaf(av[mf][0].x, b0.x, fmaf(av[mf][0].y, b0.y, acc1[mf][nf].x));
                acc1[mf][nf].y = fmaf(av[mf][0].x, b1.x, fmaf(av[mf][0].y, b1.y, acc1[mf][nf].y));
                acc1[mf][nf].z = fmaf(av[mf][1].x, b0.x, fmaf(av[mf][1].y, b0.y, acc1[mf][nf].z));
                acc1[mf][nf].w = fmaf(av[mf][1].x, b1.x, fmaf(av[mf][1].y, b1.y, acc1[mf][nf].w));
                acc2[mf][nf].x = fmaf(av[mf][0].x, d0.x, fmaf(av[mf][0].y, d0.y, acc2[mf][nf].x));
                acc2[mf][nf].y = fmaf(av[mf][0].x, d1.x, fmaf(av[mf][0].y, d1.y, acc2[mf][nf].y));
                acc2[mf][nf].z = fmaf(av[mf][1].x, d0.x, fmaf(av[mf][1].y, d0.y, acc2[mf][nf].z));
                acc2[mf][nf].w = fmaf(av[mf][1].x, d1.x, fmaf(av[mf][1].y, d1.y, acc2[mf][nf].w));
            }
        }
    };

    int slot = 0;
    for (int it = 0; it < niter; ++it) {
        if (it + 2 < niter)
            load_stage((it + 2) % 3, it + 2);
        asm volatile("cp.async.commit_group;\n");
        asm volatile("cp.async.wait_group 2;\n");
        __syncthreads();

        const char* st = sm + slot * STAGEB;
        const __half* As = reinterpret_cast<const __half*>(st);
        const __half* B1s = reinterpret_cast<const __half*>(st + 12288);
        const __half* B2s = reinterpret_cast<const __half*>(st + 18432);

        #pragma unroll
        for (int ks = 0; ks < 2; ks++) {
            const int ko = ks * 16 + 4 * tig;
            uint2 alo[2], ahi[2];
            #pragma unroll
            for (int mf = 0; mf < 2; mf++) {
                const int r = wm * 32 + mf * 16 + gid;
                alo[mf] = *reinterpret_cast<const uint2*>(As + r * 48 + ko);
                ahi[mf] = *reinterpret_cast<const uint2*>(As + (r + 8) * 48 + ko);
            }
            #pragma unroll
            for (int nf = 0; nf < 4; nf++) {
                const int n = wn * 32 + nf * 8 + gid;
                const uint2 bv = *reinterpret_cast<const uint2*>(B1s + n * 48 + ko);
                uint2 cv;
                if (DUAL) cv = *reinterpret_cast<const uint2*>(B2s + n * 48 + ko);
                #pragma unroll
                for (int mf = 0; mf < 2; mf++) {
                    mma_f16(acc1[mf][nf], alo[mf].x, ahi[mf].x, alo[mf].y, ahi[mf].y,
                            bv.x, bv.y);
                    if (DUAL)
                        mma_f16(acc2[mf][nf], alo[mf].x, ahi[mf].x, alo[mf].y, ahi[mf].y,
                                cv.x, cv.y);
                }
            }
        }

        if (HYB) {
            ffma_pair(it);                       // pairs 0..29
            if (it < 2) ffma_pair(30 + it);      // pairs 30,31
        }

        __syncthreads();
        slot = (slot + 1 == 3) ? 0 : slot + 1;
    }

    // ------------------------------ Epilogue ------------------------------
    float2* stg = reinterpret_cast<float2*>(sm);

    #pragma unroll
    for (int nf = 0; nf < 4; nf++) {
        const int cl0 = wn * 32 + nf * 8 + 2 * tig;       // local col (even)
        const int c0 = bn + cl0;
        const float bias1a = b1[c0], bias1b = b1[c0 + 1];
        float bias2a = 0.f, bias2b = 0.f;
        if (DUAL) { bias2a = b2[c0]; bias2b = b2[c0 + 1]; }
        float decaya = 0.f, decayb = 0.f;
        if (MODE == 0) {
            const float inv = 1.0f / (float)(N - 1);
            decaya = (float)c0 * inv;
            decayb = (float)(c0 + 1) * inv;
        }
        #pragma unroll
        for (int mf = 0; mf < 2; mf++) {
            const float4 a1 = acc1[mf][nf];
            const float4 a2 = acc2[mf][nf];
            #pragma unroll
            for (int h = 0; h < 2; h++) {
                const int rl = wm * 32 + mf * 16 + gid + h * 8;   // local row
                const int r = bm + rl;
                const float z1a = (h ? a1.z : a1.x) + bias1a;
                const float z1b = (h ? a1.w : a1.y) + bias1b;
                if (MODE == 0) {
                    const float z2a = (h ? a2.z : a2.x) + bias2a;
                    const float z2b = (h ? a2.w : a2.y) + bias2b;
                    const float rema = decaya * sigmoidf_(z1a);
                    const float remb = decayb * sigmoidf_(z1b);
                    const float ria = rema * tanhf(z2a);
                    const float rib = remb * tanhf(z2b);
                    // quantize FIRST so aggregates match scan_apply exactly
                    const __half2 rem_h = __floats2half2_rn(rema, remb);
                    const __half2 ri_h  = __floats2half2_rn(ria, rib);
                    uint2 pk;
                    pk.x = *reinterpret_cast<const uint32_t*>(&rem_h);
                    pk.y = *reinterpret_cast<const uint32_t*>(&ri_h);
                    rirm[((size_t)r * N + c0) >> 1] = pk;
                    const float2 rem_q = __half22float2(rem_h);
                    const float2 ri_q  = __half22float2(ri_h);
                    stg[rl * 65 + cl0]     = make_float2(1.0f - rem_q.x, ri_q.x);
                    stg[rl * 65 + cl0 + 1] = make_float2(1.0f - rem_q.y, ri_q.y);
                } else if (MODE == 1) {
                    const float z2a = (h ? a2.z : a2.x) + bias2a;
                    const float z2b = (h ? a2.w : a2.y) + bias2b;
                    const float va = z1a * (z2a * sigmoidf_(z2a));
                    const float vb = z1b * (z2b * sigmoidf_(z2b));
                    __half* fo = reinterpret_cast<__half*>(out) + (size_t)r * N;
                    *reinterpret_cast<__half2*>(fo + psl(c0)) = __floats2half2_rn(va, vb);
                } else if (MODE == 2) {
                    const size_t idx = (size_t)r * N + c0;
                    const float2 rv = *reinterpret_cast<const float2*>(res + idx);
                    __half* xo = reinterpret_cast<__half*>(out);
                    *reinterpret_cast<__half2*>(xo + idx) =
                        __floats2half2_rn(z1a + rv.x, z1b + rv.y);
                } else {
                    const size_t idx = (size_t)r * N + c0;
                    const float2 rv =
                        __half22float2(*reinterpret_cast<const __half2*>(resh + idx));
                    float2 o;
                    o.x = z1a + rv.x;
                    o.y = z1b + rv.y;
                    *reinterpret_cast<float2*>(out + idx) = o;
                }
            }
        }
    }

    if (MODE == 0) {
        // Fused chunk-scan: 128 chains (2 chunks x 64 cols), 64 steps each.
        __syncthreads();
        if (tid < 128) {
            const int chunk = tid >> 6;      // 0..1
            const int col = tid & 63;        // 0..63
            const float2* p = stg + (chunk * 64) * 65 + col;
            float a = 1.0f, s = 0.0f;
            #pragma unroll 8
            for (int rr = 0; rr < 64; rr++) {
                const float2 v = p[rr * 65];
                s = fmaf(v.x, s, v.y);
                a *= v.x;
            }
            const int b = bm >> 12;                       // bm / 4096
            const int cglob = ((bm & 4095) >> 6) + chunk; // chunk index in b
            ab[((size_t)(b * 64 + cglob) << 11) + bn + col] = make_float2(a, s);
        }
    }
    (void)M;
}

// ---------------------------------------------------------------------------
// Cross-chunk carry: one thread per channel, 16-wide batched AB prefetch.
// ---------------------------------------------------------------------------
__global__ void __launch_bounds__(256) scan_carry(
    const float2* __restrict__ ab,
    const float* __restrict__ hidden,
    float* __restrict__ cin,
    float* __restrict__ hlast)
{
    const int idx = blockIdx.x * 256 + threadIdx.x;   // 0 .. B*H-1
    const int b = idx >> 11;
    const int h = idx & (Hc - 1);
    float carry = hidden[idx];
    const float2* pab = ab + ((size_t)(b * 64) << 11) + h;
    float* pc = cin + ((size_t)(b * 64) << 11) + h;
    for (int c0 = 0; c0 < 64; c0 += 16) {
        float2 v[16];
        #pragma unroll
        for (int u = 0; u < 16; u++) v[u] = pab[(size_t)(c0 + u) << 11];
        #pragma unroll
        for (int u = 0; u < 16; u++) {
            pc[(size_t)(c0 + u) << 11] = carry;
            carry = fmaf(v[u].x, carry, v[u].y);
        }
    }
    hlast[idx] = carry;
}

// ---------------------------------------------------------------------------
// Re-apply with correct carry-in; channel pairs from the interleaved RIRM
// plane (one 8B load per step); f = 1 - rem (fp32 exact).
// HBUF written k-permuted fp16. 16-deep load batches for MLP.
// ---------------------------------------------------------------------------
__global__ void __launch_bounds__(256) scan_apply(
    const uint2* __restrict__ rirm,
    const float2* __restrict__ cin2,
    __half2* __restrict__ hbuf2)
{
    const int idx = blockIdx.x * 256 + threadIdx.x;   // B*64*1024 pairs
    const int hp = idx & 1023;
    const int rest = idx >> 10;
    const int c = rest & 63;
    const int b = rest >> 6;
    const size_t offp = ((size_t)b * Lc + (size_t)c * 64) * (Hc / 2);  // in pairs
    const uint2* pm = rirm + offp + hp;
    __half2* o = hbuf2 + offp + (psl(2 * hp) >> 1);
    float2 carry = cin2[idx];
    for (int t = 0; t < 64; t += 16) {
        uint2 v[16];
        #pragma unroll
        for (int u = 0; u < 16; u++)
            v[u] = pm[(size_t)(t + u) * (Hc / 2)];
        #pragma unroll
        for (int u = 0; u < 16; u++) {
            const float2 mv = __half22float2(*reinterpret_cast<const __half2*>(&v[u].x));
            const float2 rv = __half22float2(*reinterpret_cast<const __half2*>(&v[u].y));
            carry.x = fmaf(1.0f - mv.x, carry.x, rv.x);
            carry.y = fmaf(1.0f - mv.y, carry.y, rv.y);
            o[(size_t)(t + u) * (Hc / 2)] = __floats2half2_rn(carry.x, carry.y);
        }
    }
}

// ---------------------------------------------------------------------------
// kernel_launch
// ---------------------------------------------------------------------------
extern "C" void kernel_launch(void* const* d_in, const int* in_sizes, int n_in,
                              void* d_out, int out_size)
{
    const float* x        = (const float*)d_in[0];
    const float* hidden   = (const float*)d_in[1];
    const float* w_forget = (const float*)d_in[2];
    const float* b_forget = (const float*)d_in[3];
    const float* w_input  = (const float*)d_in[4];
    const float* b_input  = (const float*)d_in[5];
    const float* w_hout   = (const float*)d_in[6];
    const float* b_hout   = (const float*)d_in[7];
    const float* w_fc     = (const float*)d_in[8];
    const float* b_fc     = (const float*)d_in[9];
    const float* w_fc_act = (const float*)d_in[10];
    const float* b_fc_act = (const float*)d_in[11];
    const float* w_fout   = (const float*)d_in[12];
    const float* b_fout   = (const float*)d_in[13];
    const float* g_norm1  = (const float*)d_in[14];
    const float* g_norm2  = (const float*)d_in[15];
    float* out = (float*)d_out;

    float* gbuf = nullptr;
    cudaGetSymbolAddress((void**)&gbuf, g_buf);
    uint2*  RIRM = (uint2*)(gbuf + OFF_RIRM);
    __half* HBUF = (__half*)(gbuf + OFF_HBUF);
    __half* X1h  = (__half*)(gbuf + OFF_X1);
    __half* XN   = (__half*)(gbuf + OFF_XN);
    __half* XN2  = (__half*)(gbuf + OFF_XN2);
    __half* FF   = (__half*)(gbuf + OFF_FF);
    __half* WT   = (__half*)(gbuf + OFF_WT);
    float*  AB   = gbuf + OFF_AB;
    float*  CIN  = gbuf + OFF_CIN;

    const int smem_dual   = 3 * 24576 + 36864;  // 110592 (pipeline + FFMA slice)
    const int smem_single = 3 * 18432;          // 55296
    static bool attr_done = false;
    if (!attr_done) {
        cudaFuncSetAttribute(gemm_f16<0>, cudaFuncAttributeMaxDynamicSharedMemorySize, smem_dual);
        cudaFuncSetAttribute(gemm_f16<1>, cudaFuncAttributeMaxDynamicSharedMemorySize, smem_dual);
        cudaFuncSetAttribute(gemm_f16<2>, cudaFuncAttributeMaxDynamicSharedMemorySize, smem_single);
        cudaFuncSetAttribute(gemm_f16<3>, cudaFuncAttributeMaxDynamicSharedMemorySize, smem_single);
        attr_done = true;
    }

    const __half* Wf   = WT + 0 * WSEG_H;
    const __half* Wi   = WT + 1 * WSEG_H;
    const __half* Who  = WT + 2 * WSEG_H;
    const __half* Wfc  = WT + 3 * WSEG_H;
    const __half* Wfca = WT + 4 * WSEG_H;
    const __half* Wfo  = WT + 5 * WSEG_H;

    // 0+1. fused: xn = fp16(rmsnorm(x)*g1)  AND  weight fp16-permute prep
    norm1_prep<<<Mrows + 12288, 256>>>(
        x, g_norm1, XN,
        w_forget, w_input, w_hout, w_fc, w_fc_act, w_fout, WT);

    // 2. dual GEMM (hybrid tensor+FFMA) -> interleaved (rem,ri) + aggregates
    gemm_f16<0><<<dim3(Hc / 64, Mrows / 128), 256, smem_dual>>>(
        XN, Wf, Wi, b_forget, b_input, nullptr, nullptr, nullptr,
        RIRM, (float2*)AB, Mrows, Hc, Dc);

    // 3. carry across chunks (h_last -> output tail), then re-apply
    scan_carry<<<(Bc * Hc) / 256, 256>>>(
        (const float2*)AB, hidden, CIN, out + BLD);
    scan_apply<<<(Bc * 64 * Hc / 2) / 256, 256>>>(
        (const uint2*)RIRM, (const float2*)CIN, (__half2*)HBUF);

    // 4. x1 = fp16( h @ w_hout^T + b_hout + x )   (plain fp16 out)
    gemm_f16<2><<<dim3(Dc / 64, Mrows / 128), 256, smem_single>>>(
        HBUF, Who, nullptr, b_hout, nullptr, x, nullptr, (float*)X1h,
        nullptr, nullptr, Mrows, Dc, Hc);

    // 5. xn2 = fp16(rmsnorm(x1) * g2), k-permuted  (fp16 input)
    rmsnorm_h_kernel<<<Mrows, 256>>>(X1h, g_norm2, XN2);

    // 6. dual GEMM (hybrid) -> ff = fc * silu(fc_act)  (fp16 permuted out)
    gemm_f16<1><<<dim3(Hc / 64, Mrows / 128), 256, smem_dual>>>(
        XN2, Wfc, Wfca, b_fc, b_fc_act, nullptr, nullptr, (float*)FF,
        nullptr, nullptr, Mrows, Hc, Dc);

    // 7. out = ff @ w_fout^T + b_fout + x1   (fp32 out, fp16 residual)
    gemm_f16<3><<<dim3(Dc / 64, Mrows / 128), 256, smem_single>>>(
        FF, Wfo, nullptr, b_fout, nullptr, nullptr, X1h, out,
        nullptr, nullptr, Mrows, Dc, Hc);

    (void)in_sizes; (void)n_in; (void)out_size;
}

// round 15
// speedup vs baseline: 1.2656x; 1.2656x over previous
#include <cuda_runtime.h>
#include <cuda_fp16.h>
#include <math.h>
#include <stdint.h>

// Problem shape (fixed by setup_inputs)
#define Bc 4
#define Lc 4096
#define Dc 1024
#define Hc 2048
#define Mrows (Bc * Lc)            // 16384
#define BLD ((size_t)Mrows * Dc)   // 16,777,216

// ---------------------------------------------------------------------------
// Scratch regions (float units)
//   RIRM uint2 [16384,1024] (rem,ri) pairs @ 0         (33,554,432 floats)
//   HBUF half [16384,2048] permuted      @ 33554432   (16,777,216 floats)
//   X1   fp16 [16384,1024] plain         @ 50331648   ( 8,388,608 floats used)
//   XN   half [16384,1024] permuted      @ 67108864   ( 8,388,608 floats)
//   XN2  half [16384,1024] permuted      @ 75497472   ( 8,388,608 floats)
//   FF   half [16384,2048] permuted      @ 83886080   (16,777,216 floats)
//   WT   half 6 x 2,097,152 permuted     @ 100663296  ( 6,291,456 floats)
//   AB   float2 [4*64*2048]              @ 106954752  ( 1,048,576 floats)
//   CIN  float  [4*64*2048]              @ 108003328  (   524,288 floats)
// total 108,527,616 floats = 434 MB
// ---------------------------------------------------------------------------
__device__ float g_buf[108527616];

#define OFF_RIRM ((size_t)0)
#define OFF_HBUF ((size_t)33554432)
#define OFF_X1   ((size_t)50331648)
#define OFF_XN   ((size_t)67108864)
#define OFF_XN2  ((size_t)75497472)
#define OFF_FF   ((size_t)83886080)
#define OFF_WT   ((size_t)100663296)
#define OFF_AB   ((size_t)106954752)
#define OFF_CIN  ((size_t)108003328)

#define WSEG_H ((size_t)2097152)   // halfs per weight matrix

// ---------------------------------------------------------------------------
// helpers
// ---------------------------------------------------------------------------
__device__ __forceinline__ float sigmoidf_(float x) {
    return 1.0f / (1.0f + expf(-x));
}
__device__ __forceinline__ void cp16(void* dst, const void* src) {
    uint32_t d = (uint32_t)__cvta_generic_to_shared(dst);
    asm volatile("cp.async.cg.shared.global [%0], [%1], 16;\n" :: "r"(d), "l"(src));
}

// k-permuted fp16 storage: within each 16-k block, pair order
// [0,1,8,9,2,3,10,11,4,5,12,13,6,7,14,15]. psl(k) for even k gives the stored
// index of that pair's first element (odd partner is psl(k)+1).
__device__ __forceinline__ int psl(int k) {
    const int p = (k >> 1) & 7;
    return (k & ~15) | ((((p & 3) << 1) | (p >> 2)) << 1);
}

__device__ __forceinline__ void mma_f16(float4& c, uint32_t a0, uint32_t a1,
                                        uint32_t a2, uint32_t a3,
                                        uint32_t b0, uint32_t b1) {
    asm volatile(
        "mma.sync.aligned.m16n8k16.row.col.f32.f16.f16.f32 "
        "{%0,%1,%2,%3}, {%4,%5,%6,%7}, {%8,%9}, {%0,%1,%2,%3};\n"
        : "+f"(c.x), "+f"(c.y), "+f"(c.z), "+f"(c.w)
        : "r"(a0), "r"(a1), "r"(a2), "r"(a3), "r"(b0), "r"(b1));
}

// ---------------------------------------------------------------------------
// Fused: rmsnorm of x (blocks [0, Mrows)) + weight fp16-permute prep
// (blocks [Mrows, Mrows+12288)). Removes one serialized launch.
// ---------------------------------------------------------------------------
__global__ void __launch_bounds__(256) norm1_prep(
    const float* __restrict__ x, const float* __restrict__ g,
    __half* __restrict__ outx,
    const float* __restrict__ w0, const float* __restrict__ w1,
    const float* __restrict__ w2, const float* __restrict__ w3,
    const float* __restrict__ w4, const float* __restrict__ w5,
    __half* __restrict__ wdst)
{
    const int t = threadIdx.x;
    if (blockIdx.x < Mrows) {
        const int row = blockIdx.x;
        const float4* xr = reinterpret_cast<const float4*>(x) + (size_t)row * (Dc / 4);
        float4 v = xr[t];
        float ss = v.x * v.x + v.y * v.y + v.z * v.z + v.w * v.w;
        #pragma unroll
        for (int off = 16; off > 0; off >>= 1)
            ss += __shfl_down_sync(0xffffffffu, ss, off);
        __shared__ float warp_s[8];
        if ((t & 31) == 0) warp_s[t >> 5] = ss;
        __syncthreads();
        float tot = 0.f;
        #pragma unroll
        for (int i = 0; i < 8; i++) tot += warp_s[i];
        const float scale = rsqrtf(tot * (1.0f / Dc) + 1e-6f);
        float4 gv = reinterpret_cast<const float4*>(g)[t];
        __half* d = outx + (size_t)row * Dc;
        const int k = 4 * t;
        *reinterpret_cast<__half2*>(d + psl(k)) =
            __floats2half2_rn(v.x * scale * gv.x, v.y * scale * gv.y);
        *reinterpret_cast<__half2*>(d + psl(k + 2)) =
            __floats2half2_rn(v.z * scale * gv.z, v.w * scale * gv.w);
    } else {
        const size_t i4 = (size_t)(blockIdx.x - Mrows) * 256 + t;
        const int seg = (int)(i4 >> 19);            // 524288 float4 per matrix
        const size_t off = (i4 & 524287) * 4;
        const float* src;
        switch (seg) {
            case 0: src = w0; break; case 1: src = w1; break;
            case 2: src = w2; break; case 3: src = w3; break;
            case 4: src = w4; break; default: src = w5; break;
        }
        float4 v = *reinterpret_cast<const float4*>(src + off);
        __half* d = wdst + seg * WSEG_H + (off & ~(size_t)15);
        const int j = (int)(off & 15);
        *reinterpret_cast<__half2*>(d + (psl(j) & 15))     = __floats2half2_rn(v.x, v.y);
        *reinterpret_cast<__half2*>(d + (psl(j + 2) & 15)) = __floats2half2_rn(v.z, v.w);
    }
}

// ---------------------------------------------------------------------------
// RMSNorm: fp16 (plain) in -> k-permuted fp16 out (used for norm2 on X1)
// ---------------------------------------------------------------------------
__global__ void __launch_bounds__(256) rmsnorm_h_kernel(
    const __half* __restrict__ x, const float* __restrict__ g,
    __half* __restrict__ out)
{
    const int row = blockIdx.x;
    const int t = threadIdx.x;
    const __half2* xr = reinterpret_cast<const __half2*>(x + (size_t)row * Dc);
    const __half2 h0 = xr[2 * t];
    const __half2 h1 = xr[2 * t + 1];
    const float2 v01 = __half22float2(h0);
    const float2 v23 = __half22float2(h1);
    float ss = v01.x * v01.x + v01.y * v01.y + v23.x * v23.x + v23.y * v23.y;
    #pragma unroll
    for (int off = 16; off > 0; off >>= 1)
        ss += __shfl_down_sync(0xffffffffu, ss, off);
    __shared__ float warp_s[8];
    if ((t & 31) == 0) warp_s[t >> 5] = ss;
    __syncthreads();
    float tot = 0.f;
    #pragma unroll
    for (int i = 0; i < 8; i++) tot += warp_s[i];
    const float scale = rsqrtf(tot * (1.0f / Dc) + 1e-6f);
    float4 gv = reinterpret_cast<const float4*>(g)[t];
    __half* d = out + (size_t)row * Dc;
    const int k = 4 * t;
    *reinterpret_cast<__half2*>(d + psl(k)) =
        __floats2half2_rn(v01.x * scale * gv.x, v01.y * scale * gv.y);
    *reinterpret_cast<__half2*>(d + psl(k + 2)) =
        __floats2half2_rn(v23.x * scale * gv.z, v23.y * scale * gv.w);
}

// ---------------------------------------------------------------------------
// fp16 HMMA GEMM: C[M,N] = epilogue(A[M,K] @ W[N,K]^T)
// A, W are k-permuted fp16. BM=128, BN=64, BK=32, 256 threads
// (8 warps: 4m x 2n), warp tile 32x32, m16n8k16 HMMA, fp32 accumulate.
// 3-stage cp.async pipeline; smem row stride 96 B -> conflict-free LDS.64.
// MODE 0: dual -> RIRM interleaved (rem,ri) fp16 pairs (quantize-then-
//         aggregate), PLUS fused per-chunk (A,S) scan aggregates to AB.
// MODE 1: dual -> FF = fp16 permuted( z1 * silu(z2) )
// MODE 2: single -> x1 = fp16( z1 + bias + fp32 residual )   (plain fp16 out)
// MODE 3: single -> out = fp32 z1 + bias + fp16 residual
// ---------------------------------------------------------------------------
template <int MODE>
__global__ void __launch_bounds__(256, 2) gemm_f16(
    const __half* __restrict__ A,
    const __half* __restrict__ W1,
    const __half* __restrict__ W2,
    const float* __restrict__ b1,
    const float* __restrict__ b2,
    const float* __restrict__ res,   // MODE2: fp32 residual
    const __half* __restrict__ resh, // MODE3: fp16 residual
    float* __restrict__ out,         // MODE1/2: __half* underneath
    uint2* __restrict__ rirm,        // MODE0: interleaved (rem,ri) plane
    float2* __restrict__ ab,         // MODE0: chunk aggregates
    int M, int N, int K)
{
    constexpr bool DUAL = (MODE == 0 || MODE == 1);
    constexpr int STAGEB = DUAL ? 24576 : 18432;  // bytes per stage
    extern __shared__ char sm[];

    const int tid  = threadIdx.x;
    const int lane = tid & 31;
    const int wid  = tid >> 5;
    const int wm = wid >> 1;           // 0..3
    const int wn = wid & 1;            // 0..1
    const int gid = lane >> 2;         // 0..7
    const int tig = lane & 3;          // 0..3
    const int bm = blockIdx.y * 128;
    const int bn = blockIdx.x * 64;
    const int niter = K >> 5;

    float4 acc1[2][4];
    float4 acc2[2][4];
    #pragma unroll
    for (int i = 0; i < 2; i++)
        #pragma unroll
        for (int j = 0; j < 4; j++) {
            acc1[i][j] = make_float4(0.f, 0.f, 0.f, 0.f);
            acc2[i][j] = make_float4(0.f, 0.f, 0.f, 0.f);
        }

    auto load_stage = [&](int slot, int it) {
        char* st = sm + slot * STAGEB;
        const int k0 = it << 5;
        #pragma unroll
        for (int i = 0; i < 2; i++) {
            int q = tid + (i << 8);
            int r = q >> 2, c = q & 3;
            cp16(st + r * 96 + c * 16, A + (size_t)(bm + r) * K + k0 + c * 8);
        }
        {
            int r = tid >> 2, c = tid & 3;
            cp16(st + 12288 + r * 96 + c * 16,
                 W1 + (size_t)(bn + r) * K + k0 + c * 8);
            if (DUAL)
                cp16(st + 18432 + r * 96 + c * 16,
                     W2 + (size_t)(bn + r) * K + k0 + c * 8);
        }
    };

    load_stage(0, 0);
    asm volatile("cp.async.commit_group;\n");
    load_stage(1, 1);
    asm volatile("cp.async.commit_group;\n");

    int slot = 0;
    for (int it = 0; it < niter; ++it) {
        if (it + 2 < niter)
            load_stage((it + 2) % 3, it + 2);
        asm volatile("cp.async.commit_group;\n");
        asm volatile("cp.async.wait_group 2;\n");
        __syncthreads();

        const char* st = sm + slot * STAGEB;
        const __half* As = reinterpret_cast<const __half*>(st);
        const __half* B1s = reinterpret_cast<const __half*>(st + 12288);
        const __half* B2s = reinterpret_cast<const __half*>(st + 18432);

        #pragma unroll
        for (int ks = 0; ks < 2; ks++) {
            const int ko = ks * 16 + 4 * tig;
            uint2 alo[2], ahi[2];
            #pragma unroll
            for (int mf = 0; mf < 2; mf++) {
                const int r = wm * 32 + mf * 16 + gid;
                alo[mf] = *reinterpret_cast<const uint2*>(As + r * 48 + ko);
                ahi[mf] = *reinterpret_cast<const uint2*>(As + (r + 8) * 48 + ko);
            }
            #pragma unroll
            for (int nf = 0; nf < 4; nf++) {
                const int n = wn * 32 + nf * 8 + gid;
                const uint2 bv = *reinterpret_cast<const uint2*>(B1s + n * 48 + ko);
                uint2 cv;
                if (DUAL) cv = *reinterpret_cast<const uint2*>(B2s + n * 48 + ko);
                #pragma unroll
                for (int mf = 0; mf < 2; mf++) {
                    mma_f16(acc1[mf][nf], alo[mf].x, ahi[mf].x, alo[mf].y, ahi[mf].y,
                            bv.x, bv.y);
                    if (DUAL)
                        mma_f16(acc2[mf][nf], alo[mf].x, ahi[mf].x, alo[mf].y, ahi[mf].y,
                                cv.x, cv.y);
                }
            }
        }
        __syncthreads();
        slot = (slot + 1 == 3) ? 0 : slot + 1;
    }

    // ------------------------------ Epilogue ------------------------------
    // MODE0 staging for the fused chunk-scan: float2 (f, ri) per cell,
    // row stride 65 float2 -> 66560 B <= 73728 B pipeline smem.
    float2* stg = reinterpret_cast<float2*>(sm);

    #pragma unroll
    for (int nf = 0; nf < 4; nf++) {
        const int cl0 = wn * 32 + nf * 8 + 2 * tig;       // local col (even)
        const int c0 = bn + cl0;
        const float bias1a = b1[c0], bias1b = b1[c0 + 1];
        float bias2a = 0.f, bias2b = 0.f;
        if (DUAL) { bias2a = b2[c0]; bias2b = b2[c0 + 1]; }
        float decaya = 0.f, decayb = 0.f;
        if (MODE == 0) {
            const float inv = 1.0f / (float)(N - 1);
            decaya = (float)c0 * inv;
            decayb = (float)(c0 + 1) * inv;
        }
        #pragma unroll
        for (int mf = 0; mf < 2; mf++) {
            const float4 a1 = acc1[mf][nf];
            const float4 a2 = acc2[mf][nf];
            #pragma unroll
            for (int h = 0; h < 2; h++) {
                const int rl = wm * 32 + mf * 16 + gid + h * 8;   // local row
                const int r = bm + rl;
                const float z1a = (h ? a1.z : a1.x) + bias1a;
                const float z1b = (h ? a1.w : a1.y) + bias1b;
                if (MODE == 0) {
                    const float z2a = (h ? a2.z : a2.x) + bias2a;
                    const float z2b = (h ? a2.w : a2.y) + bias2b;
                    const float rema = decaya * sigmoidf_(z1a);
                    const float remb = decayb * sigmoidf_(z1b);
                    const float ria = rema * tanhf(z2a);
                    const float rib = remb * tanhf(z2b);
                    // quantize FIRST so aggregates match scan_apply exactly
                    const __half2 rem_h = __floats2half2_rn(rema, remb);
                    const __half2 ri_h  = __floats2half2_rn(ria, rib);
                    uint2 pk;
                    pk.x = *reinterpret_cast<const uint32_t*>(&rem_h);
                    pk.y = *reinterpret_cast<const uint32_t*>(&ri_h);
                    rirm[((size_t)r * N + c0) >> 1] = pk;
                    const float2 rem_q = __half22float2(rem_h);
                    const float2 ri_q  = __half22float2(ri_h);
                    stg[rl * 65 + cl0]     = make_float2(1.0f - rem_q.x, ri_q.x);
                    stg[rl * 65 + cl0 + 1] = make_float2(1.0f - rem_q.y, ri_q.y);
                } else if (MODE == 1) {
                    const float z2a = (h ? a2.z : a2.x) + bias2a;
                    const float z2b = (h ? a2.w : a2.y) + bias2b;
                    const float va = z1a * (z2a * sigmoidf_(z2a));
                    const float vb = z1b * (z2b * sigmoidf_(z2b));
                    __half* fo = reinterpret_cast<__half*>(out) + (size_t)r * N;
                    *reinterpret_cast<__half2*>(fo + psl(c0)) = __floats2half2_rn(va, vb);
                } else if (MODE == 2) {
                    const size_t idx = (size_t)r * N + c0;
                    const float2 rv = *reinterpret_cast<const float2*>(res + idx);
                    __half* xo = reinterpret_cast<__half*>(out);
                    *reinterpret_cast<__half2*>(xo + idx) =
                        __floats2half2_rn(z1a + rv.x, z1b + rv.y);
                } else {
                    const size_t idx = (size_t)r * N + c0;
                    const float2 rv =
                        __half22float2(*reinterpret_cast<const __half2*>(resh + idx));
                    float2 o;
                    o.x = z1a + rv.x;
                    o.y = z1b + rv.y;
                    *reinterpret_cast<float2*>(out + idx) = o;
                }
            }
        }
    }

    if (MODE == 0) {
        // Fused chunk-scan: 128 chains (2 chunks x 64 cols), 64 steps each.
        __syncthreads();
        if (tid < 128) {
            const int chunk = tid >> 6;      // 0..1
            const int col = tid & 63;        // 0..63
            const float2* p = stg + (chunk * 64) * 65 + col;
            float a = 1.0f, s = 0.0f;
            #pragma unroll 8
            for (int rr = 0; rr < 64; rr++) {
                const float2 v = p[rr * 65];
                s = fmaf(v.x, s, v.y);
                a *= v.x;
            }
            const int b = bm >> 12;                       // bm / 4096
            const int cglob = ((bm & 4095) >> 6) + chunk; // chunk index in b
            ab[((size_t)(b * 64 + cglob) << 11) + bn + col] = make_float2(a, s);
        }
    }
    (void)M;
}

// ---------------------------------------------------------------------------
// Cross-chunk carry: one thread per channel, 16-wide batched AB prefetch.
// ---------------------------------------------------------------------------
__global__ void __launch_bounds__(256) scan_carry(
    const float2* __restrict__ ab,
    const float* __restrict__ hidden,
    float* __restrict__ cin,
    float* __restrict__ hlast)
{
    const int idx = blockIdx.x * 256 + threadIdx.x;   // 0 .. B*H-1
    const int b = idx >> 11;
    const int h = idx & (Hc - 1);
    float carry = hidden[idx];
    const float2* pab = ab + ((size_t)(b * 64) << 11) + h;
    float* pc = cin + ((size_t)(b * 64) << 11) + h;
    for (int c0 = 0; c0 < 64; c0 += 16) {
        float2 v[16];
        #pragma unroll
        for (int u = 0; u < 16; u++) v[u] = pab[(size_t)(c0 + u) << 11];
        #pragma unroll
        for (int u = 0; u < 16; u++) {
            pc[(size_t)(c0 + u) << 11] = carry;
            carry = fmaf(v[u].x, carry, v[u].y);
        }
    }
    hlast[idx] = carry;
}

// ---------------------------------------------------------------------------
// Re-apply with correct carry-in; channel pairs from the interleaved RIRM
// plane (one 8B load per step); f = 1 - rem (fp32 exact).
// HBUF written k-permuted fp16. 16-deep load batches for MLP.
// ---------------------------------------------------------------------------
__global__ void __launch_bounds__(256) scan_apply(
    const uint2* __restrict__ rirm,
    const float2* __restrict__ cin2,
    __half2* __restrict__ hbuf2)
{
    const int idx = blockIdx.x * 256 + threadIdx.x;   // B*64*1024 pairs
    const int hp = idx & 1023;
    const int rest = idx >> 10;
    const int c = rest & 63;
    const int b = rest >> 6;
    const size_t offp = ((size_t)b * Lc + (size_t)c * 64) * (Hc / 2);  // in pairs
    const uint2* pm = rirm + offp + hp;
    __half2* o = hbuf2 + offp + (psl(2 * hp) >> 1);
    float2 carry = cin2[idx];
    for (int t = 0; t < 64; t += 16) {
        uint2 v[16];
        #pragma unroll
        for (int u = 0; u < 16; u++)
            v[u] = pm[(size_t)(t + u) * (Hc / 2)];
        #pragma unroll
        for (int u = 0; u < 16; u++) {
            const float2 mv = __half22float2(*reinterpret_cast<const __half2*>(&v[u].x));
            const float2 rv = __half22float2(*reinterpret_cast<const __half2*>(&v[u].y));
            carry.x = fmaf(1.0f - mv.x, carry.x, rv.x);
            carry.y = fmaf(1.0f - mv.y, carry.y, rv.y);
            o[(size_t)(t + u) * (Hc / 2)] = __floats2half2_rn(carry.x, carry.y);
        }
    }
}

// ---------------------------------------------------------------------------
// kernel_launch
// ---------------------------------------------------------------------------
extern "C" void kernel_launch(void* const* d_in, const int* in_sizes, int n_in,
                              void* d_out, int out_size)
{
    const float* x        = (const float*)d_in[0];
    const float* hidden   = (const float*)d_in[1];
    const float* w_forget = (const float*)d_in[2];
    const float* b_forget = (const float*)d_in[3];
    const float* w_input  = (const float*)d_in[4];
    const float* b_input  = (const float*)d_in[5];
    const float* w_hout   = (const float*)d_in[6];
    const float* b_hout   = (const float*)d_in[7];
    const float* w_fc     = (const float*)d_in[8];
    const float* b_fc     = (const float*)d_in[9];
    const float* w_fc_act = (const float*)d_in[10];
    const float* b_fc_act = (const float*)d_in[11];
    const float* w_fout   = (const float*)d_in[12];
    const float* b_fout   = (const float*)d_in[13];
    const float* g_norm1  = (const float*)d_in[14];
    const float* g_norm2  = (const float*)d_in[15];
    float* out = (float*)d_out;

    float* gbuf = nullptr;
    cudaGetSymbolAddress((void**)&gbuf, g_buf);
    uint2*  RIRM = (uint2*)(gbuf + OFF_RIRM);
    __half* HBUF = (__half*)(gbuf + OFF_HBUF);
    __half* X1h  = (__half*)(gbuf + OFF_X1);
    __half* XN   = (__half*)(gbuf + OFF_XN);
    __half* XN2  = (__half*)(gbuf + OFF_XN2);
    __half* FF   = (__half*)(gbuf + OFF_FF);
    __half* WT   = (__half*)(gbuf + OFF_WT);
    float*  AB   = gbuf + OFF_AB;
    float*  CIN  = gbuf + OFF_CIN;

    const int smem_dual   = 3 * 24576;  // 73728
    const int smem_single = 3 * 18432;  // 55296
    static bool attr_done = false;
    if (!attr_done) {
        cudaFuncSetAttribute(gemm_f16<0>, cudaFuncAttributeMaxDynamicSharedMemorySize, smem_dual);
        cudaFuncSetAttribute(gemm_f16<1>, cudaFuncAttributeMaxDynamicSharedMemorySize, smem_dual);
        cudaFuncSetAttribute(gemm_f16<2>, cudaFuncAttributeMaxDynamicSharedMemorySize, smem_single);
        cudaFuncSetAttribute(gemm_f16<3>, cudaFuncAttributeMaxDynamicSharedMemorySize, smem_single);
        attr_done = true;
    }

    const __half* Wf   = WT + 0 * WSEG_H;
    const __half* Wi   = WT + 1 * WSEG_H;
    const __half* Who  = WT + 2 * WSEG_H;
    const __half* Wfc  = WT + 3 * WSEG_H;
    const __half* Wfca = WT + 4 * WSEG_H;
    const __half* Wfo  = WT + 5 * WSEG_H;

    // 0+1. fused: xn = fp16(rmsnorm(x)*g1)  AND  weight fp16-permute prep
    norm1_prep<<<Mrows + 12288, 256>>>(
        x, g_norm1, XN,
        w_forget, w_input, w_hout, w_fc, w_fc_act, w_fout, WT);

    // 2. dual GEMM -> interleaved (rem,ri) + fused chunk aggregates
    gemm_f16<0><<<dim3(Hc / 64, Mrows / 128), 256, smem_dual>>>(
        XN, Wf, Wi, b_forget, b_input, nullptr, nullptr, nullptr,
        RIRM, (float2*)AB, Mrows, Hc, Dc);

    // 3. carry across chunks (h_last -> output tail), then re-apply
    scan_carry<<<(Bc * Hc) / 256, 256>>>(
        (const float2*)AB, hidden, CIN, out + BLD);
    scan_apply<<<(Bc * 64 * Hc / 2) / 256, 256>>>(
        (const uint2*)RIRM, (const float2*)CIN, (__half2*)HBUF);

    // 4. x1 = fp16( h @ w_hout^T + b_hout + x )   (plain fp16 out)
    gemm_f16<2><<<dim3(Dc / 64, Mrows / 128), 256, smem_single>>>(
        HBUF, Who, nullptr, b_hout, nullptr, x, nullptr, (float*)X1h,
        nullptr, nullptr, Mrows, Dc, Hc);

    // 5. xn2 = fp16(rmsnorm(x1) * g2), k-permuted  (fp16 input)
    rmsnorm_h_kernel<<<Mrows, 256>>>(X1h, g_norm2, XN2);

    // 6. dual GEMM -> ff = fc * silu(fc_act)  (fp16 permuted out)
    gemm_f16<1><<<dim3(Hc / 64, Mrows / 128), 256, smem_dual>>>(
        XN2, Wfc, Wfca, b_fc, b_fc_act, nullptr, nullptr, (float*)FF,
        nullptr, nullptr, Mrows, Hc, Dc);

    // 7. out = ff @ w_fout^T + b_fout + x1   (fp32 out, fp16 residual)
    gemm_f16<3><<<dim3(Dc / 64, Mrows / 128), 256, smem_single>>>(
        FF, Wfo, nullptr, b_fout, nullptr, nullptr, X1h, out,
        nullptr, nullptr, Mrows, Dc, Hc);

    (void)in_sizes; (void)n_in; (void)out_size;
}

// round 16
// speedup vs baseline: 1.2668x; 1.0009x over previous
#include <cuda_runtime.h>
#include <cuda_fp16.h>
#include <math.h>
#include <stdint.h>

// Problem shape (fixed by setup_inputs)
#define Bc 4
#define Lc 4096
#define Dc 1024
#define Hc 2048
#define Mrows (Bc * Lc)            // 16384
#define BLD ((size_t)Mrows * Dc)   // 16,777,216

// ---------------------------------------------------------------------------
// Scratch regions (float units)
//   RIRM uint2 [16384,1024] (rem,ri) pairs @ 0         (33,554,432 floats)
//   HBUF half [16384,2048] permuted      @ 33554432   (16,777,216 floats)
//   X1   fp16 [16384,1024] plain         @ 50331648   ( 8,388,608 floats used)
//   XN   half [16384,1024] permuted      @ 67108864   ( 8,388,608 floats)
//   XN2  half [16384,1024] permuted      @ 75497472   ( 8,388,608 floats)
//   FF   half [16384,2048] permuted      @ 83886080   (16,777,216 floats)
//   WT   half 6 x 2,097,152 permuted     @ 100663296  ( 6,291,456 floats)
//   AB   float2 [4*64*2048]              @ 106954752  ( 1,048,576 floats)
//   CIN  float  [4*64*2048]              @ 108003328  (   524,288 floats)
// total 108,527,616 floats = 434 MB
// ---------------------------------------------------------------------------
__device__ float g_buf[108527616];

#define OFF_RIRM ((size_t)0)
#define OFF_HBUF ((size_t)33554432)
#define OFF_X1   ((size_t)50331648)
#define OFF_XN   ((size_t)67108864)
#define OFF_XN2  ((size_t)75497472)
#define OFF_FF   ((size_t)83886080)
#define OFF_WT   ((size_t)100663296)
#define OFF_AB   ((size_t)106954752)
#define OFF_CIN  ((size_t)108003328)

#define WSEG_H ((size_t)2097152)   // halfs per weight matrix

// ---------------------------------------------------------------------------
// helpers
// ---------------------------------------------------------------------------
__device__ __forceinline__ float sigmoidf_(float x) {
    return 1.0f / (1.0f + expf(-x));
}
__device__ __forceinline__ void cp16(void* dst, const void* src) {
    uint32_t d = (uint32_t)__cvta_generic_to_shared(dst);
    asm volatile("cp.async.cg.shared.global [%0], [%1], 16;\n" :: "r"(d), "l"(src));
}

// k-permuted fp16 storage: within each 16-k block, pair order
// [0,1,8,9,2,3,10,11,4,5,12,13,6,7,14,15]. psl(k) for even k gives the stored
// index of that pair's first element (odd partner is psl(k)+1).
__device__ __forceinline__ int psl(int k) {
    const int p = (k >> 1) & 7;
    return (k & ~15) | ((((p & 3) << 1) | (p >> 2)) << 1);
}

// Convert one float4 of weight data into k-permuted fp16 at dst segment.
__device__ __forceinline__ void prep_one(const float* __restrict__ src,
                                         __half* __restrict__ dseg,
                                         size_t off) {
    float4 v = *reinterpret_cast<const float4*>(src + off);
    __half* d = dseg + (off & ~(size_t)15);
    const int j = (int)(off & 15);
    *reinterpret_cast<__half2*>(d + (psl(j) & 15))     = __floats2half2_rn(v.x, v.y);
    *reinterpret_cast<__half2*>(d + (psl(j + 2) & 15)) = __floats2half2_rn(v.z, v.w);
}

__device__ __forceinline__ void mma_f16(float4& c, uint32_t a0, uint32_t a1,
                                        uint32_t a2, uint32_t a3,
                                        uint32_t b0, uint32_t b1) {
    asm volatile(
        "mma.sync.aligned.m16n8k16.row.col.f32.f16.f16.f32 "
        "{%0,%1,%2,%3}, {%4,%5,%6,%7}, {%8,%9}, {%0,%1,%2,%3};\n"
        : "+f"(c.x), "+f"(c.y), "+f"(c.z), "+f"(c.w)
        : "r"(a0), "r"(a1), "r"(a2), "r"(a3), "r"(b0), "r"(b1));
}

// ---------------------------------------------------------------------------
// Fused: rmsnorm of x (blocks [0, Mrows)) + fp16-permute prep of w_forget and
// w_input only (blocks [Mrows, Mrows+4096)) — the two weights GEMM0 needs.
// The 4 late weights are prepped inside scan_carry's grid (hidden under the
// post-GEMM0 latency-bound carry pass).
// ---------------------------------------------------------------------------
__global__ void __launch_bounds__(256) norm1_prep(
    const float* __restrict__ x, const float* __restrict__ g,
    __half* __restrict__ outx,
    const float* __restrict__ w0, const float* __restrict__ w1,
    __half* __restrict__ wdst)
{
    const int t = threadIdx.x;
    if (blockIdx.x < Mrows) {
        const int row = blockIdx.x;
        const float4* xr = reinterpret_cast<const float4*>(x) + (size_t)row * (Dc / 4);
        float4 v = xr[t];
        float ss = v.x * v.x + v.y * v.y + v.z * v.z + v.w * v.w;
        #pragma unroll
        for (int off = 16; off > 0; off >>= 1)
            ss += __shfl_down_sync(0xffffffffu, ss, off);
        __shared__ float warp_s[8];
        if ((t & 31) == 0) warp_s[t >> 5] = ss;
        __syncthreads();
        float tot = 0.f;
        #pragma unroll
        for (int i = 0; i < 8; i++) tot += warp_s[i];
        const float scale = rsqrtf(tot * (1.0f / Dc) + 1e-6f);
        float4 gv = reinterpret_cast<const float4*>(g)[t];
        __half* d = outx + (size_t)row * Dc;
        const int k = 4 * t;
        *reinterpret_cast<__half2*>(d + psl(k)) =
            __floats2half2_rn(v.x * scale * gv.x, v.y * scale * gv.y);
        *reinterpret_cast<__half2*>(d + psl(k + 2)) =
            __floats2half2_rn(v.z * scale * gv.z, v.w * scale * gv.w);
    } else {
        const size_t i4 = (size_t)(blockIdx.x - Mrows) * 256 + t;   // < 1,048,576
        const int seg = (int)(i4 >> 19);            // 0 or 1
        const size_t off = (i4 & 524287) * 4;
        prep_one(seg == 0 ? w0 : w1, wdst + (size_t)seg * WSEG_H, off);
    }
}

// ---------------------------------------------------------------------------
// RMSNorm: fp16 (plain) in -> k-permuted fp16 out (used for norm2 on X1)
// ---------------------------------------------------------------------------
__global__ void __launch_bounds__(256) rmsnorm_h_kernel(
    const __half* __restrict__ x, const float* __restrict__ g,
    __half* __restrict__ out)
{
    const int row = blockIdx.x;
    const int t = threadIdx.x;
    const __half2* xr = reinterpret_cast<const __half2*>(x + (size_t)row * Dc);
    const __half2 h0 = xr[2 * t];
    const __half2 h1 = xr[2 * t + 1];
    const float2 v01 = __half22float2(h0);
    const float2 v23 = __half22float2(h1);
    float ss = v01.x * v01.x + v01.y * v01.y + v23.x * v23.x + v23.y * v23.y;
    #pragma unroll
    for (int off = 16; off > 0; off >>= 1)
        ss += __shfl_down_sync(0xffffffffu, ss, off);
    __shared__ float warp_s[8];
    if ((t & 31) == 0) warp_s[t >> 5] = ss;
    __syncthreads();
    float tot = 0.f;
    #pragma unroll
    for (int i = 0; i < 8; i++) tot += warp_s[i];
    const float scale = rsqrtf(tot * (1.0f / Dc) + 1e-6f);
    float4 gv = reinterpret_cast<const float4*>(g)[t];
    __half* d = out + (size_t)row * Dc;
    const int k = 4 * t;
    *reinterpret_cast<__half2*>(d + psl(k)) =
        __floats2half2_rn(v01.x * scale * gv.x, v01.y * scale * gv.y);
    *reinterpret_cast<__half2*>(d + psl(k + 2)) =
        __floats2half2_rn(v23.x * scale * gv.z, v23.y * scale * gv.w);
}

// ---------------------------------------------------------------------------
// fp16 HMMA GEMM: C[M,N] = epilogue(A[M,K] @ W[N,K]^T)
// A, W are k-permuted fp16. BM=128, BN=64, BK=32, 256 threads
// (8 warps: 4m x 2n), warp tile 32x32, m16n8k16 HMMA, fp32 accumulate.
// 3-stage cp.async pipeline; smem row stride 96 B -> conflict-free LDS.64.
// MODE 0: dual -> RIRM interleaved (rem,ri) fp16 pairs (quantize-then-
//         aggregate), PLUS fused per-chunk (A,S) scan aggregates to AB.
// MODE 1: dual -> FF = fp16 permuted( z1 * silu(z2) )
// MODE 2: single -> x1 = fp16( z1 + bias + fp32 residual )   (plain fp16 out)
// MODE 3: single -> out = fp32 z1 + bias + fp16 residual
// ---------------------------------------------------------------------------
template <int MODE>
__global__ void __launch_bounds__(256, 2) gemm_f16(
    const __half* __restrict__ A,
    const __half* __restrict__ W1,
    const __half* __restrict__ W2,
    const float* __restrict__ b1,
    const float* __restrict__ b2,
    const float* __restrict__ res,   // MODE2: fp32 residual
    const __half* __restrict__ resh, // MODE3: fp16 residual
    float* __restrict__ out,         // MODE1/2: __half* underneath
    uint2* __restrict__ rirm,        // MODE0: interleaved (rem,ri) plane
    float2* __restrict__ ab,         // MODE0: chunk aggregates
    int M, int N, int K)
{
    constexpr bool DUAL = (MODE == 0 || MODE == 1);
    constexpr int STAGEB = DUAL ? 24576 : 18432;  // bytes per stage
    extern __shared__ char sm[];

    const int tid  = threadIdx.x;
    const int lane = tid & 31;
    const int wid  = tid >> 5;
    const int wm = wid >> 1;           // 0..3
    const int wn = wid & 1;            // 0..1
    const int gid = lane >> 2;         // 0..7
    const int tig = lane & 3;          // 0..3
    const int bm = blockIdx.y * 128;
    const int bn = blockIdx.x * 64;
    const int niter = K >> 5;

    float4 acc1[2][4];
    float4 acc2[2][4];
    #pragma unroll
    for (int i = 0; i < 2; i++)
        #pragma unroll
        for (int j = 0; j < 4; j++) {
            acc1[i][j] = make_float4(0.f, 0.f, 0.f, 0.f);
            acc2[i][j] = make_float4(0.f, 0.f, 0.f, 0.f);
        }

    auto load_stage = [&](int slot, int it) {
        char* st = sm + slot * STAGEB;
        const int k0 = it << 5;
        #pragma unroll
        for (int i = 0; i < 2; i++) {
            int q = tid + (i << 8);
            int r = q >> 2, c = q & 3;
            cp16(st + r * 96 + c * 16, A + (size_t)(bm + r) * K + k0 + c * 8);
        }
        {
            int r = tid >> 2, c = tid & 3;
            cp16(st + 12288 + r * 96 + c * 16,
                 W1 + (size_t)(bn + r) * K + k0 + c * 8);
            if (DUAL)
                cp16(st + 18432 + r * 96 + c * 16,
                     W2 + (size_t)(bn + r) * K + k0 + c * 8);
        }
    };

    load_stage(0, 0);
    asm volatile("cp.async.commit_group;\n");
    load_stage(1, 1);
    asm volatile("cp.async.commit_group;\n");

    int slot = 0;
    for (int it = 0; it < niter; ++it) {
        if (it + 2 < niter)
            load_stage((it + 2) % 3, it + 2);
        asm volatile("cp.async.commit_group;\n");
        asm volatile("cp.async.wait_group 2;\n");
        __syncthreads();

        const char* st = sm + slot * STAGEB;
        const __half* As = reinterpret_cast<const __half*>(st);
        const __half* B1s = reinterpret_cast<const __half*>(st + 12288);
        const __half* B2s = reinterpret_cast<const __half*>(st + 18432);

        #pragma unroll
        for (int ks = 0; ks < 2; ks++) {
            const int ko = ks * 16 + 4 * tig;
            uint2 alo[2], ahi[2];
            #pragma unroll
            for (int mf = 0; mf < 2; mf++) {
                const int r = wm * 32 + mf * 16 + gid;
                alo[mf] = *reinterpret_cast<const uint2*>(As + r * 48 + ko);
                ahi[mf] = *reinterpret_cast<const uint2*>(As + (r + 8) * 48 + ko);
            }
            #pragma unroll
            for (int nf = 0; nf < 4; nf++) {
                const int n = wn * 32 + nf * 8 + gid;
                const uint2 bv = *reinterpret_cast<const uint2*>(B1s + n * 48 + ko);
                uint2 cv;
                if (DUAL) cv = *reinterpret_cast<const uint2*>(B2s + n * 48 + ko);
                #pragma unroll
                for (int mf = 0; mf < 2; mf++) {
                    mma_f16(acc1[mf][nf], alo[mf].x, ahi[mf].x, alo[mf].y, ahi[mf].y,
                            bv.x, bv.y);
                    if (DUAL)
                        mma_f16(acc2[mf][nf], alo[mf].x, ahi[mf].x, alo[mf].y, ahi[mf].y,
                                cv.x, cv.y);
                }
            }
        }
        __syncthreads();
        slot = (slot + 1 == 3) ? 0 : slot + 1;
    }

    // ------------------------------ Epilogue ------------------------------
    // MODE0 staging for the fused chunk-scan: float2 (f, ri) per cell,
    // row stride 65 float2 -> 66560 B <= 73728 B pipeline smem.
    float2* stg = reinterpret_cast<float2*>(sm);

    #pragma unroll
    for (int nf = 0; nf < 4; nf++) {
        const int cl0 = wn * 32 + nf * 8 + 2 * tig;       // local col (even)
        const int c0 = bn + cl0;
        const float bias1a = b1[c0], bias1b = b1[c0 + 1];
        float bias2a = 0.f, bias2b = 0.f;
        if (DUAL) { bias2a = b2[c0]; bias2b = b2[c0 + 1]; }
        float decaya = 0.f, decayb = 0.f;
        if (MODE == 0) {
            const float inv = 1.0f / (float)(N - 1);
            decaya = (float)c0 * inv;
            decayb = (float)(c0 + 1) * inv;
        }
        #pragma unroll
        for (int mf = 0; mf < 2; mf++) {
            const float4 a1 = acc1[mf][nf];
            const float4 a2 = acc2[mf][nf];
            #pragma unroll
            for (int h = 0; h < 2; h++) {
                const int rl = wm * 32 + mf * 16 + gid + h * 8;   // local row
                const int r = bm + rl;
                const float z1a = (h ? a1.z : a1.x) + bias1a;
                const float z1b = (h ? a1.w : a1.y) + bias1b;
                if (MODE == 0) {
                    const float z2a = (h ? a2.z : a2.x) + bias2a;
                    const float z2b = (h ? a2.w : a2.y) + bias2b;
                    const float rema = decaya * sigmoidf_(z1a);
                    const float remb = decayb * sigmoidf_(z1b);
                    const float ria = rema * tanhf(z2a);
                    const float rib = remb * tanhf(z2b);
                    // quantize FIRST so aggregates match scan_apply exactly
                    const __half2 rem_h = __floats2half2_rn(rema, remb);
                    const __half2 ri_h  = __floats2half2_rn(ria, rib);
                    uint2 pk;
                    pk.x = *reinterpret_cast<const uint32_t*>(&rem_h);
                    pk.y = *reinterpret_cast<const uint32_t*>(&ri_h);
                    rirm[((size_t)r * N + c0) >> 1] = pk;
                    const float2 rem_q = __half22float2(rem_h);
                    const float2 ri_q  = __half22float2(ri_h);
                    stg[rl * 65 + cl0]     = make_float2(1.0f - rem_q.x, ri_q.x);
                    stg[rl * 65 + cl0 + 1] = make_float2(1.0f - rem_q.y, ri_q.y);
                } else if (MODE == 1) {
                    const float z2a = (h ? a2.z : a2.x) + bias2a;
                    const float z2b = (h ? a2.w : a2.y) + bias2b;
                    const float va = z1a * (z2a * sigmoidf_(z2a));
                    const float vb = z1b * (z2b * sigmoidf_(z2b));
                    __half* fo = reinterpret_cast<__half*>(out) + (size_t)r * N;
                    *reinterpret_cast<__half2*>(fo + psl(c0)) = __floats2half2_rn(va, vb);
                } else if (MODE == 2) {
                    const size_t idx = (size_t)r * N + c0;
                    const float2 rv = *reinterpret_cast<const float2*>(res + idx);
                    __half* xo = reinterpret_cast<__half*>(out);
                    *reinterpret_cast<__half2*>(xo + idx) =
                        __floats2half2_rn(z1a + rv.x, z1b + rv.y);
                } else {
                    const size_t idx = (size_t)r * N + c0;
                    const float2 rv =
                        __half22float2(*reinterpret_cast<const __half2*>(resh + idx));
                    float2 o;
                    o.x = z1a + rv.x;
                    o.y = z1b + rv.y;
                    *reinterpret_cast<float2*>(out + idx) = o;
                }
            }
        }
    }

    if (MODE == 0) {
        // Fused chunk-scan: 128 chains (2 chunks x 64 cols), 64 steps each.
        __syncthreads();
        if (tid < 128) {
            const int chunk = tid >> 6;      // 0..1
            const int col = tid & 63;        // 0..63
            const float2* p = stg + (chunk * 64) * 65 + col;
            float a = 1.0f, s = 0.0f;
            #pragma unroll 8
            for (int rr = 0; rr < 64; rr++) {
                const float2 v = p[rr * 65];
                s = fmaf(v.x, s, v.y);
                a *= v.x;
            }
            const int b = bm >> 12;                       // bm / 4096
            const int cglob = ((bm & 4095) >> 6) + chunk; // chunk index in b
            ab[((size_t)(b * 64 + cglob) << 11) + bn + col] = make_float2(a, s);
        }
    }
    (void)M;
}

// ---------------------------------------------------------------------------
// Cross-chunk carry (blocks [0,32)) + fp16-permute prep of the 4 late weights
// (blocks [32, 32+8192)). The carry pass uses only 8192 threads; the prep
// CTAs fill the otherwise-idle chip right after GEMM0.
// ---------------------------------------------------------------------------
__global__ void __launch_bounds__(256) scan_carry(
    const float2* __restrict__ ab,
    const float* __restrict__ hidden,
    float* __restrict__ cin,
    float* __restrict__ hlast,
    const float* __restrict__ w2, const float* __restrict__ w3,
    const float* __restrict__ w4, const float* __restrict__ w5,
    __half* __restrict__ wdst)
{
    if (blockIdx.x >= 32) {
        // Weight prep: 8192 blocks x 256 threads = 2,097,152 float4 (segs 2..5)
        const size_t i4 = (size_t)(blockIdx.x - 32) * 256 + threadIdx.x;
        const int seg = (int)(i4 >> 19);            // 0..3
        const size_t off = (i4 & 524287) * 4;
        const float* src = (seg == 0) ? w2 : (seg == 1) ? w3
                         : (seg == 2) ? w4 : w5;
        prep_one(src, wdst + (size_t)(seg + 2) * WSEG_H, off);
        return;
    }
    const int idx = blockIdx.x * 256 + threadIdx.x;   // 0 .. B*H-1
    const int b = idx >> 11;
    const int h = idx & (Hc - 1);
    float carry = hidden[idx];
    const float2* pab = ab + ((size_t)(b * 64) << 11) + h;
    float* pc = cin + ((size_t)(b * 64) << 11) + h;
    for (int c0 = 0; c0 < 64; c0 += 16) {
        float2 v[16];
        #pragma unroll
        for (int u = 0; u < 16; u++) v[u] = pab[(size_t)(c0 + u) << 11];
        #pragma unroll
        for (int u = 0; u < 16; u++) {
            pc[(size_t)(c0 + u) << 11] = carry;
            carry = fmaf(v[u].x, carry, v[u].y);
        }
    }
    hlast[idx] = carry;
}

// ---------------------------------------------------------------------------
// Re-apply with correct carry-in; channel pairs from the interleaved RIRM
// plane (one 8B load per step); f = 1 - rem (fp32 exact).
// HBUF written k-permuted fp16. 16-deep load batches for MLP.
// ---------------------------------------------------------------------------
__global__ void __launch_bounds__(256) scan_apply(
    const uint2* __restrict__ rirm,
    const float2* __restrict__ cin2,
    __half2* __restrict__ hbuf2)
{
    const int idx = blockIdx.x * 256 + threadIdx.x;   // B*64*1024 pairs
    const int hp = idx & 1023;
    const int rest = idx >> 10;
    const int c = rest & 63;
    const int b = rest >> 6;
    const size_t offp = ((size_t)b * Lc + (size_t)c * 64) * (Hc / 2);  // in pairs
    const uint2* pm = rirm + offp + hp;
    __half2* o = hbuf2 + offp + (psl(2 * hp) >> 1);
    float2 carry = cin2[idx];
    for (int t = 0; t < 64; t += 16) {
        uint2 v[16];
        #pragma unroll
        for (int u = 0; u < 16; u++)
            v[u] = pm[(size_t)(t + u) * (Hc / 2)];
        #pragma unroll
        for (int u = 0; u < 16; u++) {
            const float2 mv = __half22float2(*reinterpret_cast<const __half2*>(&v[u].x));
            const float2 rv = __half22float2(*reinterpret_cast<const __half2*>(&v[u].y));
            carry.x = fmaf(1.0f - mv.x, carry.x, rv.x);
            carry.y = fmaf(1.0f - mv.y, carry.y, rv.y);
            o[(size_t)(t + u) * (Hc / 2)] = __floats2half2_rn(carry.x, carry.y);
        }
    }
}

// ---------------------------------------------------------------------------
// kernel_launch
// ---------------------------------------------------------------------------
extern "C" void kernel_launch(void* const* d_in, const int* in_sizes, int n_in,
                              void* d_out, int out_size)
{
    const float* x        = (const float*)d_in[0];
    const float* hidden   = (const float*)d_in[1];
    const float* w_forget = (const float*)d_in[2];
    const float* b_forget = (const float*)d_in[3];
    const float* w_input  = (const float*)d_in[4];
    const float* b_input  = (const float*)d_in[5];
    const float* w_hout   = (const float*)d_in[6];
    const float* b_hout   = (const float*)d_in[7];
    const float* w_fc     = (const float*)d_in[8];
    const float* b_fc     = (const float*)d_in[9];
    const float* w_fc_act = (const float*)d_in[10];
    const float* b_fc_act = (const float*)d_in[11];
    const float* w_fout   = (const float*)d_in[12];
    const float* b_fout   = (const float*)d_in[13];
    const float* g_norm1  = (const float*)d_in[14];
    const float* g_norm2  = (const float*)d_in[15];
    float* out = (float*)d_out;

    float* gbuf = nullptr;
    cudaGetSymbolAddress((void**)&gbuf, g_buf);
    uint2*  RIRM = (uint2*)(gbuf + OFF_RIRM);
    __half* HBUF = (__half*)(gbuf + OFF_HBUF);
    __half* X1h  = (__half*)(gbuf + OFF_X1);
    __half* XN   = (__half*)(gbuf + OFF_XN);
    __half* XN2  = (__half*)(gbuf + OFF_XN2);
    __half* FF   = (__half*)(gbuf + OFF_FF);
    __half* WT   = (__half*)(gbuf + OFF_WT);
    float*  AB   = gbuf + OFF_AB;
    float*  CIN  = gbuf + OFF_CIN;

    const int smem_dual   = 3 * 24576;  // 73728
    const int smem_single = 3 * 18432;  // 55296
    static bool attr_done = false;
    if (!attr_done) {
        cudaFuncSetAttribute(gemm_f16<0>, cudaFuncAttributeMaxDynamicSharedMemorySize, smem_dual);
        cudaFuncSetAttribute(gemm_f16<1>, cudaFuncAttributeMaxDynamicSharedMemorySize, smem_dual);
        cudaFuncSetAttribute(gemm_f16<2>, cudaFuncAttributeMaxDynamicSharedMemorySize, smem_single);
        cudaFuncSetAttribute(gemm_f16<3>, cudaFuncAttributeMaxDynamicSharedMemorySize, smem_single);
        attr_done = true;
    }

    const __half* Wf   = WT + 0 * WSEG_H;
    const __half* Wi   = WT + 1 * WSEG_H;
    const __half* Who  = WT + 2 * WSEG_H;
    const __half* Wfc  = WT + 3 * WSEG_H;
    const __half* Wfca = WT + 4 * WSEG_H;
    const __half* Wfo  = WT + 5 * WSEG_H;

    // 0+1. fused: xn = fp16(rmsnorm(x)*g1) AND prep of w_forget/w_input only
    norm1_prep<<<Mrows + 4096, 256>>>(x, g_norm1, XN, w_forget, w_input, WT);

    // 2. dual GEMM -> interleaved (rem,ri) + fused chunk aggregates
    gemm_f16<0><<<dim3(Hc / 64, Mrows / 128), 256, smem_dual>>>(
        XN, Wf, Wi, b_forget, b_input, nullptr, nullptr, nullptr,
        RIRM, (float2*)AB, Mrows, Hc, Dc);

    // 3. carry across chunks (h_last -> output tail) + late-weight prep,
    //    then re-apply
    scan_carry<<<(Bc * Hc) / 256 + 8192, 256>>>(
        (const float2*)AB, hidden, CIN, out + BLD,
        w_hout, w_fc, w_fc_act, w_fout, WT);
    scan_apply<<<(Bc * 64 * Hc / 2) / 256, 256>>>(
        (const uint2*)RIRM, (const float2*)CIN, (__half2*)HBUF);

    // 4. x1 = fp16( h @ w_hout^T + b_hout + x )   (plain fp16 out)
    gemm_f16<2><<<dim3(Dc / 64, Mrows / 128), 256, smem_single>>>(
        HBUF, Who, nullptr, b_hout, nullptr, x, nullptr, (float*)X1h,
        nullptr, nullptr, Mrows, Dc, Hc);

    // 5. xn2 = fp16(rmsnorm(x1) * g2), k-permuted  (fp16 input)
    rmsnorm_h_kernel<<<Mrows, 256>>>(X1h, g_norm2, XN2);

    // 6. dual GEMM -> ff = fc * silu(fc_act)  (fp16 permuted out)
    gemm_f16<1><<<dim3(Hc / 64, Mrows / 128), 256, smem_dual>>>(
        XN2, Wfc, Wfca, b_fc, b_fc_act, nullptr, nullptr, (float*)FF,
        nullptr, nullptr, Mrows, Hc, Dc);

    // 7. out = ff @ w_fout^T + b_fout + x1   (fp32 out, fp16 residual)
    gemm_f16<3><<<dim3(Dc / 64, Mrows / 128), 256, smem_single>>>(
        FF, Wfo, nullptr, b_fout, nullptr, nullptr, X1h, out,
        nullptr, nullptr, Mrows, Dc, Hc);

    (void)in_sizes; (void)n_in; (void)out_size;
}